// round 16
// baseline (speedup 1.0000x reference)
#include <cuda_runtime.h>
#include <math.h>

#define Dm 256
#define Bg 256
#define SH 16
#define CHUNK 512
#define TILE 32
#define NCH 4

__device__ int   g_off[Bg + 1];
__device__ float g_As[SH * 260];
__device__ float g_csum[Bg * NCH * SH];
__device__ float g_cy[Bg * NCH * SH * Dm];      // 16 MB scratch
__device__ float g_W2T[4 * 256 * 256];          // [h][j][i]
__device__ float g_cAtt[256];
__device__ float g_fc1T[1024 * 256];            // [j][i]
__device__ float g_fc2T[256 * 256];             // [j][i]

// ---- cp.async helpers ----------------------------------------------------------
__device__ __forceinline__ void cp_async16(void* dst_smem, const void* src_gmem) {
    unsigned sa = (unsigned)__cvta_generic_to_shared(dst_smem);
    asm volatile("cp.async.cg.shared.global [%0], [%1], 16;\n" :: "r"(sa), "l"(src_gmem));
}
#define CP_COMMIT() asm volatile("cp.async.commit_group;\n" ::: "memory")
#define CP_WAIT0()  asm volatile("cp.async.wait_group 0;\n" ::: "memory")

__device__ __forceinline__ unsigned f2tf32(float x) {
    unsigned r;
    asm("cvt.rna.tf32.f32 %0, %1;" : "=r"(r) : "f"(x));
    return r;
}

__device__ __forceinline__ void mma_tf32(float* c, const unsigned* a, const unsigned* b) {
    asm volatile(
        "mma.sync.aligned.m16n8k8.row.col.f32.tf32.tf32.f32 "
        "{%0,%1,%2,%3}, {%4,%5,%6,%7}, {%8,%9}, {%0,%1,%2,%3};"
        : "+f"(c[0]), "+f"(c[1]), "+f"(c[2]), "+f"(c[3])
        : "r"(a[0]), "r"(a[1]), "r"(a[2]), "r"(a[3]), "r"(b[0]), "r"(b[1]));
}

// ---------------- k_proA: A matrix (64 blocks x 4 cols) + offsets/cAtt -----------
__global__ __launch_bounds__(256) void k_proA(const int* __restrict__ cnt,
                                              const float* __restrict__ seeds,
                                              const float* __restrict__ inW,
                                              const float* __restrict__ inB,
                                              const float* __restrict__ Wo,
                                              const float* __restrict__ bo)
{
    __shared__ float sbuf[2112];
    int bid = blockIdx.x;
    int t = threadIdx.x;

    if (bid < 64) {
        float* ss = sbuf;           // seeds, then reused for partials
        float* qs = sbuf + 1024;
        for (int i = t; i < 1024; i += 256) ss[i] = seeds[i];
        __syncthreads();
        float qa0[4] = {0.f, 0.f, 0.f, 0.f};
        float qa1[4] = {0.f, 0.f, 0.f, 0.f};
        const float4* W4 = (const float4*)inW;
        const float4* S4 = (const float4*)ss;
        #pragma unroll 16
        for (int j = 0; j < 64; j += 2) {
            float4 w0 = W4[t * 64 + j];
            float4 w1 = W4[t * 64 + j + 1];
            #pragma unroll
            for (int s = 0; s < 4; s++) {
                float4 s0 = S4[s * 64 + j];
                float4 s1 = S4[s * 64 + j + 1];
                qa0[s] += w0.x * s0.x + w0.y * s0.y + w0.z * s0.z + w0.w * s0.w;
                qa1[s] += w1.x * s1.x + w1.y * s1.y + w1.z * s1.z + w1.w * s1.w;
            }
        }
        __syncthreads();   // done reading ss (seeds) before reuse as partials
        #pragma unroll
        for (int s = 0; s < 4; s++) qs[s * 256 + t] = qa0[s] + qa1[s] + inB[t];
        __syncthreads();
        // A-phase: thread = (sh, col-of-4, k-quarter of 16)
        {
            int sh = t >> 4, rem = t & 15;
            int cc = rem >> 2, k4 = rem & 3;
            int col = bid * 4 + cc;
            int s = sh >> 2, h = sh & 3;
            const float* Wk = inW + 65536;
            const float* qrow = qs + s * 256 + h * 64 + k4 * 16;
            const float* wcol = Wk + (h * 64 + k4 * 16) * 256 + col;
            float a0 = 0.f, a1 = 0.f, a2 = 0.f, a3 = 0.f;
            #pragma unroll
            for (int d = 0; d < 16; d += 4) {
                a0 += qrow[d]     * wcol[d * 256];
                a1 += qrow[d + 1] * wcol[(d + 1) * 256];
                a2 += qrow[d + 2] * wcol[(d + 2) * 256];
                a3 += qrow[d + 3] * wcol[(d + 3) * 256];
            }
            ss[t] = a0 + a1 + a2 + a3;   // partial for (sh, cc, k4)
        }
        __syncthreads();
        if (t < 64) {
            int sh2 = t >> 2, c2 = t & 3;
            float v = ss[t * 4] + ss[t * 4 + 1] + ss[t * 4 + 2] + ss[t * 4 + 3];
            g_As[sh2 * 260 + bid * 4 + c2] = v * 0.125f;
        }
    } else {
        int* sc = (int*)sbuf;
        int c = cnt[t]; sc[t] = c; __syncthreads();
        #pragma unroll
        for (int d = 1; d < 256; d <<= 1) {
            int v = (t >= d) ? sc[t - d] : 0; __syncthreads();
            sc[t] += v; __syncthreads();
        }
        g_off[t + 1] = sc[t];
        if (t == 0) g_off[0] = 0;
        float* bvs = sbuf + 256;
        bvs[t] = inB[512 + t];
        __syncthreads();
        const float4* Wo4 = (const float4*)Wo;
        const float4* bv4 = (const float4*)bvs;
        float a = bo[t];
        #pragma unroll 8
        for (int j = 0; j < 64; j++) {
            float4 w = Wo4[t * 64 + j], v = bv4[j];
            a += w.x * v.x + w.y * v.y + w.z * v.z + w.w * v.w;
        }
        g_cAtt[t] = a;
    }
}

// ---------------- attention (+ fused prep-B blocks) — flat softmax ----------------
// dyn smem floats:
//   xs     [0, 16640)        2 bufs x 32 rows x 260 (65-f4 row stride)
//   scoreP [16640, 18816)    4 K-partials x [32][17]
//   scE    [18816, 19328)    [32][16]
#define ATTN_SMEM_F 19328
#define N_ATTN 1024
__global__ __launch_bounds__(256, 2) void k_attn(const float* __restrict__ X,
                                                 const float* __restrict__ inW,
                                                 const float* __restrict__ Wo,
                                                 const float* __restrict__ fc1w,
                                                 const float* __restrict__ fc2w)
{
    extern __shared__ __align__(16) float sm[];
    int t = threadIdx.x;
    int bid = blockIdx.x;

    if (bid >= N_ATTN) {
        // ================= prep-B blocks =================
        int pb = bid - N_ATTN;
        if (pb < 256) {
            float* wvs = sm;       // 256: [dh 0..63][jj 0..3]
            int hb = pb >> 6;
            int j0 = (pb & 63) * 4;
            const float* Wv = inW + 2 * 65536;
            { int dh = t >> 2, jj = t & 3;
              wvs[t] = Wv[(hb * 64 + dh) * Dm + j0 + jj]; }
            __syncthreads();
            const float4* Wo4 = (const float4*)Wo;
            const float4* wv4 = (const float4*)wvs;
            float a0 = 0.f, a1 = 0.f, a2 = 0.f, a3 = 0.f;
            #pragma unroll
            for (int k = 0; k < 16; k++) {
                float4 w = Wo4[t * 64 + hb * 16 + k];
                float4 v0 = wv4[k * 4 + 0], v1 = wv4[k * 4 + 1];
                float4 v2 = wv4[k * 4 + 2], v3 = wv4[k * 4 + 3];
                a0 += w.x * v0.x + w.y * v1.x + w.z * v2.x + w.w * v3.x;
                a1 += w.x * v0.y + w.y * v1.y + w.z * v2.y + w.w * v3.y;
                a2 += w.x * v0.z + w.y * v1.z + w.z * v2.z + w.w * v3.z;
                a3 += w.x * v0.w + w.y * v1.w + w.z * v2.w + w.w * v3.w;
            }
            g_W2T[(hb * 256 + j0 + 0) * 256 + t] = a0;
            g_W2T[(hb * 256 + j0 + 1) * 256 + t] = a1;
            g_W2T[(hb * 256 + j0 + 2) * 256 + t] = a2;
            g_W2T[(hb * 256 + j0 + 3) * 256 + t] = a3;
        } else {
            float (*tile)[33] = (float (*)[33])sm;
            int b3 = pb - 256;
            int tx = t & 31, ty = t >> 5;
            const float* src; float* dst; int C, c0, r0;
            if (b3 < 256) { src = fc1w; dst = g_fc1T; C = 1024; c0 = (b3 & 31) * 32; r0 = (b3 >> 5) * 32; }
            else { int b4 = b3 - 256; src = fc2w; dst = g_fc2T; C = 256; c0 = (b4 & 7) * 32; r0 = (b4 >> 3) * 32; }
            #pragma unroll
            for (int k = 0; k < 4; k++)
                tile[ty + k * 8][tx] = src[(r0 + ty + k * 8) * C + c0 + tx];
            __syncthreads();
            #pragma unroll
            for (int k = 0; k < 4; k++)
                dst[(c0 + ty + k * 8) * 256 + r0 + tx] = tile[tx][ty + k * 8];
        }
        return;
    }

    // ================= attention blocks =================
    float*  xs     = sm;
    float4* xs4    = (float4*)sm;
    float*  scoreP = sm + 16640;   // [kq][32][17]
    float*  scE    = sm + 18816;   // [n][16]

    int b = bid >> 2, c = bid & 3;
    int off = g_off[b];
    int count = g_off[b + 1] - off;
    int cstart = c * CHUNK;
    if (cstart >= count) return;
    int cend = min(count, cstart + CHUNK);
    int ntiles = (cend - cstart + TILE - 1) >> 5;

    const float4* X4 = (const float4*)X;

    // prefetch tile 0 into buffer 0
    {
        int tn0 = min(TILE, cend - cstart);
        for (int e = t; e < tn0 * 64; e += 256)
            cp_async16(&xs4[(e >> 6) * 65 + (e & 63)],
                       &X4[(size_t)(off + cstart + (e >> 6)) * 64 + (e & 63)]);
        CP_COMMIT();
    }

    int lane = t & 31;
    int w    = t >> 5;
    int g    = lane >> 2;      // groupID
    int tid4 = lane & 3;       // threadID in group
    int mh   = w & 1;          // score m-half
    int kq   = w >> 1;         // score K-quarter
    int m0   = mh * 16;

    // persistent B fragments (A-matrix)
    unsigned bf[8][2][2];
    #pragma unroll
    for (int j = 0; j < 8; j++) {
        int k0 = kq * 64 + j * 8;
        #pragma unroll
        for (int nt = 0; nt < 2; nt++) {
            int sh = nt * 8 + g;
            bf[j][nt][0] = f2tf32(g_As[sh * 260 + k0 + tid4]);
            bf[j][nt][1] = f2tf32(g_As[sh * 260 + k0 + tid4 + 4]);
        }
    }

    float runs = 0.f;
    float yc[4][4];
    #pragma unroll
    for (int nt = 0; nt < 4; nt++)
        #pragma unroll
        for (int q = 0; q < 4; q++) yc[nt][q] = 0.f;

    int mysh = w + (((t >> 4) & 1) << 3);
    int myn  = lane & 15;

    for (int i = 0; i < ntiles; i++) {
        CP_WAIT0();
        __syncthreads();
        int bi = i & 1;
        int tn = min(TILE, cend - (cstart + i * TILE));

        if (i + 1 < ntiles) {
            int ns = cstart + (i + 1) * TILE;
            int tnn = min(TILE, cend - ns);
            int bn = (i + 1) & 1;
            for (int e = t; e < tnn * 64; e += 256)
                cp_async16(&xs4[bn * 2080 + (e >> 6) * 65 + (e & 63)],
                           &X4[(size_t)(off + ns + (e >> 6)) * 64 + (e & 63)]);
        }
        CP_COMMIT();

        // ---- score phase: tf32 mma, warp = (m-half, K-quarter) ----
        {
            float acc0[4] = {0.f, 0.f, 0.f, 0.f};
            float acc1[4] = {0.f, 0.f, 0.f, 0.f};
            const float* xb = xs + bi * 8320;
            #pragma unroll
            for (int j = 0; j < 8; j++) {
                int k0 = kq * 64 + j * 8;
                const float* xa = xb + (m0 + g) * 260 + k0 + tid4;
                unsigned af[4];
                af[0] = f2tf32(xa[0]);
                af[1] = f2tf32(xa[8 * 260]);
                af[2] = f2tf32(xa[4]);
                af[3] = f2tf32(xa[8 * 260 + 4]);
                mma_tf32(acc0, af, bf[j][0]);
                mma_tf32(acc1, af, bf[j][1]);
            }
            float* sp = scoreP + kq * 544;
            int n0 = m0 + g, n1 = m0 + 8 + g;
            sp[n0 * 17 + 2 * tid4]     = acc0[0];
            sp[n0 * 17 + 2 * tid4 + 1] = acc0[1];
            sp[n1 * 17 + 2 * tid4]     = acc0[2];
            sp[n1 * 17 + 2 * tid4 + 1] = acc0[3];
            sp[n0 * 17 + 8 + 2 * tid4]     = acc1[0];
            sp[n0 * 17 + 8 + 2 * tid4 + 1] = acc1[1];
            sp[n1 * 17 + 8 + 2 * tid4]     = acc1[2];
            sp[n1 * 17 + 8 + 2 * tid4 + 1] = acc1[3];
        }
        __syncthreads();

        // ---- flat softmax: scores bounded (|s| << 60), no max needed ----
        {
            int n1 = myn, n2 = myn + 16;
            bool v1 = n1 < tn, v2 = n2 < tn;
            float e1 = 0.f, e2 = 0.f;
            if (v1) {
                float s1 = scoreP[n1 * 17 + mysh] + scoreP[544 + n1 * 17 + mysh]
                         + scoreP[1088 + n1 * 17 + mysh] + scoreP[1632 + n1 * 17 + mysh];
                e1 = __expf(s1);
            }
            if (v2) {
                float s2 = scoreP[n2 * 17 + mysh] + scoreP[544 + n2 * 17 + mysh]
                         + scoreP[1088 + n2 * 17 + mysh] + scoreP[1632 + n2 * 17 + mysh];
                e2 = __expf(s2);
            }
            scE[n1 * 16 + mysh] = e1;       // always write: zero for invalid lanes
            scE[n2 * 16 + mysh] = e2;
            float ssum = e1 + e2;
            ssum += __shfl_xor_sync(0xffffffffu, ssum, 1);
            ssum += __shfl_xor_sync(0xffffffffu, ssum, 2);
            ssum += __shfl_xor_sync(0xffffffffu, ssum, 4);
            ssum += __shfl_xor_sync(0xffffffffu, ssum, 8);
            runs += ssum;
        }
        __syncthreads();

        // ---- y-pass: tf32 mma, warp owns 32 columns (no rescale) ----
        {
            const float* xb = xs + bi * 8320;
            #pragma unroll
            for (int kk2 = 0; kk2 < 4; kk2++) {
                unsigned af[4];
                af[0] = f2tf32(scE[(kk2 * 8 + tid4) * 16 + g]);
                af[1] = f2tf32(scE[(kk2 * 8 + tid4) * 16 + g + 8]);
                af[2] = f2tf32(scE[(kk2 * 8 + tid4 + 4) * 16 + g]);
                af[3] = f2tf32(scE[(kk2 * 8 + tid4 + 4) * 16 + g + 8]);
                const float* xrow0 = xb + (kk2 * 8 + tid4) * 260 + w * 32 + g;
                const float* xrow1 = xb + (kk2 * 8 + tid4 + 4) * 260 + w * 32 + g;
                #pragma unroll
                for (int nt = 0; nt < 4; nt++) {
                    unsigned bfr[2];
                    bfr[0] = f2tf32(xrow0[nt * 8]);
                    bfr[1] = f2tf32(xrow1[nt * 8]);
                    mma_tf32(yc[nt], af, bfr);
                }
            }
        }
        // next-iteration top barrier doubles as the post-y fence
    }
    __syncthreads();

    if (myn == 0)
        g_csum[bid * 16 + mysh] = runs;
    {
        #pragma unroll
        for (int nt = 0; nt < 4; nt++) {
            int colb = w * 32 + nt * 8 + 2 * tid4;
            float* p0 = &g_cy[((size_t)bid * 16 + g) * 256 + colb];
            float* p1 = &g_cy[((size_t)bid * 16 + g + 8) * 256 + colb];
            *(float2*)p0 = make_float2(yc[nt][0], yc[nt][1]);
            *(float2*)p1 = make_float2(yc[nt][2], yc[nt][3]);
        }
    }
}

// ---------------- combine: G=4 graphs/block, 64 blocks, 512 threads --------------
// dyn smem floats: ysP[16384] att[4096] hbuf[1024] itot[64] part[8192] = 29760
#define COMB_SMEM_F 29760
__global__ __launch_bounds__(512) void k_comb(float* __restrict__ out,
                                              const float* __restrict__ fc1b,
                                              const float* __restrict__ fc2b)
{
    extern __shared__ __align__(16) float smc[];
    float* ysP  = smc;            // [g][h][col][s] as float4 over s
    float* att  = smc + 16384;    // [g][s*256+i]
    float* hbuf = smc + 20480;    // [g][i]
    float* itot = smc + 21504;    // [g*16+sh]
    float* part = smc + 21568;    // [half][16][256]

    int t = threadIdx.x;
    int col = t & 255;
    int half = t >> 8;
    int b0 = blockIdx.x * 4;

    if (t < 64) {
        int g = t >> 4, sh = t & 15;
        int b = b0 + g;
        float tot = g_csum[(b * NCH + 0) * 16 + sh] + g_csum[(b * NCH + 1) * 16 + sh]
                  + g_csum[(b * NCH + 2) * 16 + sh] + g_csum[(b * NCH + 3) * 16 + sh];
        itot[t] = 1.f / tot;
    }
    __syncthreads();

    // ysP fill: half h does sh range [h*8, h*8+8); plain sum over chunks
    #pragma unroll
    for (int g = 0; g < 4; g++) {
        int b = b0 + g;
        #pragma unroll
        for (int s8 = 0; s8 < 8; s8++) {
            int sh = half * 8 + s8;
            float acc = g_cy[((b * NCH + 0) * 16 + sh) * 256 + col]
                      + g_cy[((b * NCH + 1) * 16 + sh) * 256 + col]
                      + g_cy[((b * NCH + 2) * 16 + sh) * 256 + col]
                      + g_cy[((b * NCH + 3) * 16 + sh) * 256 + col];
            float yv = acc * itot[g * 16 + sh];
            ysP[(((g * 4 + (sh & 3)) * 256 + col) << 2) + (sh >> 2)] = yv;
        }
    }
    __syncthreads();

    // W2T phase: half h does heads {2h, 2h+1}; a[g*4+s] partials for 4 graphs
    {
        float a[16];
        #pragma unroll
        for (int i = 0; i < 16; i++) a[i] = 0.f;
        #pragma unroll
        for (int hh = 0; hh < 2; hh++) {
            int h = half * 2 + hh;
            const float* wpA = g_W2T + h * 65536 + col;
            const float* wpB = wpA + 128 * 256;
            const float4* y0 = (const float4*)ysP + (0 * 4 + h) * 256;
            const float4* y1 = (const float4*)ysP + (1 * 4 + h) * 256;
            const float4* y2 = (const float4*)ysP + (2 * 4 + h) * 256;
            const float4* y3 = (const float4*)ysP + (3 * 4 + h) * 256;
            #pragma unroll 8
            for (int j = 0; j < 128; j++) {
                float wA = wpA[j * 256];
                float wB = wpB[j * 256];
                float4 pA0 = y0[j],       pA1 = y1[j],       pA2 = y2[j],       pA3 = y3[j];
                float4 pB0 = y0[j + 128], pB1 = y1[j + 128], pB2 = y2[j + 128], pB3 = y3[j + 128];
                a[0]  += wA * pA0.x + wB * pB0.x; a[1]  += wA * pA0.y + wB * pB0.y;
                a[2]  += wA * pA0.z + wB * pB0.z; a[3]  += wA * pA0.w + wB * pB0.w;
                a[4]  += wA * pA1.x + wB * pB1.x; a[5]  += wA * pA1.y + wB * pB1.y;
                a[6]  += wA * pA1.z + wB * pB1.z; a[7]  += wA * pA1.w + wB * pB1.w;
                a[8]  += wA * pA2.x + wB * pB2.x; a[9]  += wA * pA2.y + wB * pB2.y;
                a[10] += wA * pA2.z + wB * pB2.z; a[11] += wA * pA2.w + wB * pB2.w;
                a[12] += wA * pA3.x + wB * pB3.x; a[13] += wA * pA3.y + wB * pB3.y;
                a[14] += wA * pA3.z + wB * pB3.z; a[15] += wA * pA3.w + wB * pB3.w;
            }
        }
        #pragma unroll
        for (int i = 0; i < 16; i++)
            part[half * 4096 + i * 256 + col] = a[i];
    }
    __syncthreads();
    if (half == 0) {
        float ca = g_cAtt[col];
        #pragma unroll
        for (int i = 0; i < 16; i++) {
            // i = g*4+s
            float v = part[i * 256 + col] + part[4096 + i * 256 + col] + ca;
            att[(i >> 2) * 1024 + (i & 3) * 256 + col] = v;
        }
    }
    __syncthreads();

    // fc1: half h does j range [h*512, h*512+512) for 4 graphs
    {
        float p[4] = {0.f, 0.f, 0.f, 0.f};
        const float* w1 = g_fc1T + (half * 512) * 256 + col;
        const float* at0 = att + 0 * 1024 + half * 512;
        const float* at1 = att + 1 * 1024 + half * 512;
        const float* at2 = att + 2 * 1024 + half * 512;
        const float* at3 = att + 3 * 1024 + half * 512;
        #pragma unroll 16
        for (int j = 0; j < 512; j++) {
            float wv = w1[j * 256];
            p[0] += wv * at0[j]; p[1] += wv * at1[j];
            p[2] += wv * at2[j]; p[3] += wv * at3[j];
        }
        #pragma unroll
        for (int g = 0; g < 4; g++)
            part[half * 4096 + g * 256 + col] = p[g];
    }
    __syncthreads();
    if (half == 0) {
        #pragma unroll
        for (int g = 0; g < 4; g++) {
            float pre = fc1b[col] + part[g * 256 + col] + part[4096 + g * 256 + col];
            hbuf[g * 256 + col] = 0.5f * pre * (1.f + erff(pre * 0.70710678118f));
        }
    }
    __syncthreads();

    // fc2: half h does j range [h*128, h*128+128) for 4 graphs
    {
        float o[4] = {0.f, 0.f, 0.f, 0.f};
        const float* w2 = g_fc2T + (half * 128) * 256 + col;
        const float* h0 = hbuf + 0 * 256 + half * 128;
        const float* h1 = hbuf + 1 * 256 + half * 128;
        const float* h2 = hbuf + 2 * 256 + half * 128;
        const float* h3 = hbuf + 3 * 256 + half * 128;
        #pragma unroll 16
        for (int j = 0; j < 128; j++) {
            float wv = w2[j * 256];
            o[0] += wv * h0[j]; o[1] += wv * h1[j];
            o[2] += wv * h2[j]; o[3] += wv * h3[j];
        }
        #pragma unroll
        for (int g = 0; g < 4; g++)
            part[half * 4096 + 1024 + g * 256 + col] = o[g];
    }
    __syncthreads();
    if (half == 0) {
        #pragma unroll
        for (int g = 0; g < 4; g++)
            out[(b0 + g) * 256 + col] = fc2b[col]
                + part[1024 + g * 256 + col] + part[4096 + 1024 + g * 256 + col];
    }
}

// ---------------- launch --------------------------------------------------------
extern "C" void kernel_launch(void* const* d_in, const int* in_sizes, int n_in,
                              void* d_out, int out_size)
{
    const float* X     = (const float*)d_in[0];
    const int*   cnt   = (const int*)  d_in[1];
    const float* seeds = (const float*)d_in[2];
    const float* inW   = (const float*)d_in[3];
    const float* inB   = (const float*)d_in[4];
    const float* outW  = (const float*)d_in[5];
    const float* outB  = (const float*)d_in[6];
    const float* fc1w  = (const float*)d_in[7];
    const float* fc1b  = (const float*)d_in[8];
    const float* fc2w  = (const float*)d_in[9];
    const float* fc2b  = (const float*)d_in[10];
    float* out = (float*)d_out;

    cudaFuncSetAttribute(k_attn, cudaFuncAttributeMaxDynamicSharedMemorySize,
                         ATTN_SMEM_F * 4);
    cudaFuncSetAttribute(k_comb, cudaFuncAttributeMaxDynamicSharedMemorySize,
                         COMB_SMEM_F * 4);

    k_proA<<<65, 256>>>(cnt, seeds, inW, inB, outW, outB);
    k_attn<<<N_ATTN + 576, 256, ATTN_SMEM_F * 4>>>(X, inW, outW, fc1w, fc2w);
    k_comb<<<64, 512, COMB_SMEM_F * 4>>>(out, fc1b, fc2b);
}

// round 17
// speedup vs baseline: 1.0728x; 1.0728x over previous
#include <cuda_runtime.h>
#include <math.h>

#define Dm 256
#define Bg 256
#define SH 16
#define CHUNK 512
#define TILE 32
#define NCH 4

__device__ int   g_off[Bg + 1];
__device__ float g_As[SH * 260];
__device__ float g_csum[Bg * NCH * SH];
__device__ float g_cy[Bg * NCH * SH * Dm];      // 16 MB scratch
__device__ float g_W2T[4 * 256 * 256];          // [h][j][i]
__device__ float g_cAtt[256];
__device__ float g_fc1T[1024 * 256];            // [j][i]
__device__ float g_fc2T[256 * 256];             // [j][i]

// ---- cp.async helpers ----------------------------------------------------------
__device__ __forceinline__ void cp_async16(void* dst_smem, const void* src_gmem) {
    unsigned sa = (unsigned)__cvta_generic_to_shared(dst_smem);
    asm volatile("cp.async.cg.shared.global [%0], [%1], 16;\n" :: "r"(sa), "l"(src_gmem));
}
#define CP_COMMIT() asm volatile("cp.async.commit_group;\n" ::: "memory")
#define CP_WAIT1()  asm volatile("cp.async.wait_group 1;\n" ::: "memory")

__device__ __forceinline__ unsigned f2tf32(float x) {
    unsigned r;
    asm("cvt.rna.tf32.f32 %0, %1;" : "=r"(r) : "f"(x));
    return r;
}

__device__ __forceinline__ void mma_tf32(float* c, const unsigned* a, const unsigned* b) {
    asm volatile(
        "mma.sync.aligned.m16n8k8.row.col.f32.tf32.tf32.f32 "
        "{%0,%1,%2,%3}, {%4,%5,%6,%7}, {%8,%9}, {%0,%1,%2,%3};"
        : "+f"(c[0]), "+f"(c[1]), "+f"(c[2]), "+f"(c[3])
        : "r"(a[0]), "r"(a[1]), "r"(a[2]), "r"(a[3]), "r"(b[0]), "r"(b[1]));
}

// ---------------- k_proA: A matrix (64 blocks x 4 cols) + offsets/cAtt -----------
__global__ __launch_bounds__(256) void k_proA(const int* __restrict__ cnt,
                                              const float* __restrict__ seeds,
                                              const float* __restrict__ inW,
                                              const float* __restrict__ inB,
                                              const float* __restrict__ Wo,
                                              const float* __restrict__ bo)
{
    __shared__ float sbuf[2112];
    int bid = blockIdx.x;
    int t = threadIdx.x;

    if (bid < 64) {
        float* ss = sbuf;           // seeds, then reused for partials
        float* qs = sbuf + 1024;
        for (int i = t; i < 1024; i += 256) ss[i] = seeds[i];
        __syncthreads();
        float qa0[4] = {0.f, 0.f, 0.f, 0.f};
        float qa1[4] = {0.f, 0.f, 0.f, 0.f};
        const float4* W4 = (const float4*)inW;
        const float4* S4 = (const float4*)ss;
        #pragma unroll 16
        for (int j = 0; j < 64; j += 2) {
            float4 w0 = W4[t * 64 + j];
            float4 w1 = W4[t * 64 + j + 1];
            #pragma unroll
            for (int s = 0; s < 4; s++) {
                float4 s0 = S4[s * 64 + j];
                float4 s1 = S4[s * 64 + j + 1];
                qa0[s] += w0.x * s0.x + w0.y * s0.y + w0.z * s0.z + w0.w * s0.w;
                qa1[s] += w1.x * s1.x + w1.y * s1.y + w1.z * s1.z + w1.w * s1.w;
            }
        }
        __syncthreads();   // done reading ss (seeds) before reuse as partials
        #pragma unroll
        for (int s = 0; s < 4; s++) qs[s * 256 + t] = qa0[s] + qa1[s] + inB[t];
        __syncthreads();
        // A-phase: thread = (sh, col-of-4, k-quarter of 16)
        {
            int sh = t >> 4, rem = t & 15;
            int cc = rem >> 2, k4 = rem & 3;
            int col = bid * 4 + cc;
            int s = sh >> 2, h = sh & 3;
            const float* Wk = inW + 65536;
            const float* qrow = qs + s * 256 + h * 64 + k4 * 16;
            const float* wcol = Wk + (h * 64 + k4 * 16) * 256 + col;
            float a0 = 0.f, a1 = 0.f, a2 = 0.f, a3 = 0.f;
            #pragma unroll
            for (int d = 0; d < 16; d += 4) {
                a0 += qrow[d]     * wcol[d * 256];
                a1 += qrow[d + 1] * wcol[(d + 1) * 256];
                a2 += qrow[d + 2] * wcol[(d + 2) * 256];
                a3 += qrow[d + 3] * wcol[(d + 3) * 256];
            }
            ss[t] = a0 + a1 + a2 + a3;   // partial for (sh, cc, k4)
        }
        __syncthreads();
        if (t < 64) {
            int sh2 = t >> 2, c2 = t & 3;
            float v = ss[t * 4] + ss[t * 4 + 1] + ss[t * 4 + 2] + ss[t * 4 + 3];
            g_As[sh2 * 260 + bid * 4 + c2] = v * 0.125f;
        }
    } else {
        int* sc = (int*)sbuf;
        int c = cnt[t]; sc[t] = c; __syncthreads();
        #pragma unroll
        for (int d = 1; d < 256; d <<= 1) {
            int v = (t >= d) ? sc[t - d] : 0; __syncthreads();
            sc[t] += v; __syncthreads();
        }
        g_off[t + 1] = sc[t];
        if (t == 0) g_off[0] = 0;
        float* bvs = sbuf + 256;
        bvs[t] = inB[512 + t];
        __syncthreads();
        const float4* Wo4 = (const float4*)Wo;
        const float4* bv4 = (const float4*)bvs;
        float a = bo[t];
        #pragma unroll 8
        for (int j = 0; j < 64; j++) {
            float4 w = Wo4[t * 64 + j], v = bv4[j];
            a += w.x * v.x + w.y * v.y + w.z * v.z + w.w * v.w;
        }
        g_cAtt[t] = a;
    }
}

// ---------------- attention (+ fused prep-B blocks) — 3-buffer pipeline ----------
// dyn smem floats:
//   xs     [0, 24960)        3 bufs x 32 rows x 260 (65-f4 row stride)
//   scoreP [24960, 27136)    4 K-partials x [32][17]
//   scE    [27136, 27648)    [32][16]
#define ATTN_SMEM_F 27648
#define N_ATTN 1024
__global__ __launch_bounds__(256, 2) void k_attn(const float* __restrict__ X,
                                                 const float* __restrict__ inW,
                                                 const float* __restrict__ Wo,
                                                 const float* __restrict__ fc1w,
                                                 const float* __restrict__ fc2w)
{
    extern __shared__ __align__(16) float sm[];
    int t = threadIdx.x;
    int bid = blockIdx.x;

    if (bid >= N_ATTN) {
        // ================= prep-B blocks =================
        int pb = bid - N_ATTN;
        if (pb < 256) {
            float* wvs = sm;       // 256: [dh 0..63][jj 0..3]
            int hb = pb >> 6;
            int j0 = (pb & 63) * 4;
            const float* Wv = inW + 2 * 65536;
            { int dh = t >> 2, jj = t & 3;
              wvs[t] = Wv[(hb * 64 + dh) * Dm + j0 + jj]; }
            __syncthreads();
            const float4* Wo4 = (const float4*)Wo;
            const float4* wv4 = (const float4*)wvs;
            float a0 = 0.f, a1 = 0.f, a2 = 0.f, a3 = 0.f;
            #pragma unroll
            for (int k = 0; k < 16; k++) {
                float4 w = Wo4[t * 64 + hb * 16 + k];
                float4 v0 = wv4[k * 4 + 0], v1 = wv4[k * 4 + 1];
                float4 v2 = wv4[k * 4 + 2], v3 = wv4[k * 4 + 3];
                a0 += w.x * v0.x + w.y * v1.x + w.z * v2.x + w.w * v3.x;
                a1 += w.x * v0.y + w.y * v1.y + w.z * v2.y + w.w * v3.y;
                a2 += w.x * v0.z + w.y * v1.z + w.z * v2.z + w.w * v3.z;
                a3 += w.x * v0.w + w.y * v1.w + w.z * v2.w + w.w * v3.w;
            }
            g_W2T[(hb * 256 + j0 + 0) * 256 + t] = a0;
            g_W2T[(hb * 256 + j0 + 1) * 256 + t] = a1;
            g_W2T[(hb * 256 + j0 + 2) * 256 + t] = a2;
            g_W2T[(hb * 256 + j0 + 3) * 256 + t] = a3;
        } else {
            float (*tile)[33] = (float (*)[33])sm;
            int b3 = pb - 256;
            int tx = t & 31, ty = t >> 5;
            const float* src; float* dst; int C, c0, r0;
            if (b3 < 256) { src = fc1w; dst = g_fc1T; C = 1024; c0 = (b3 & 31) * 32; r0 = (b3 >> 5) * 32; }
            else { int b4 = b3 - 256; src = fc2w; dst = g_fc2T; C = 256; c0 = (b4 & 7) * 32; r0 = (b4 >> 3) * 32; }
            #pragma unroll
            for (int k = 0; k < 4; k++)
                tile[ty + k * 8][tx] = src[(r0 + ty + k * 8) * C + c0 + tx];
            __syncthreads();
            #pragma unroll
            for (int k = 0; k < 4; k++)
                dst[(c0 + ty + k * 8) * 256 + r0 + tx] = tile[tx][ty + k * 8];
        }
        return;
    }

    // ================= attention blocks =================
    float*  xs     = sm;
    float4* xs4    = (float4*)sm;
    float*  scoreP = sm + 24960;   // [kq][32][17]
    float*  scE    = sm + 27136;   // [n][16]

    int b = bid >> 2, c = bid & 3;
    int off = g_off[b];
    int count = g_off[b + 1] - off;
    int cstart = c * CHUNK;
    if (cstart >= count) return;
    int cend = min(count, cstart + CHUNK);
    int ntiles = (cend - cstart + TILE - 1) >> 5;

    const float4* X4 = (const float4*)X;

    // prologue: prefetch tiles 0 and 1 (two commit groups, possibly empty second)
    {
        int tn0 = min(TILE, cend - cstart);
        for (int e = t; e < tn0 * 64; e += 256)
            cp_async16(&xs4[(e >> 6) * 65 + (e & 63)],
                       &X4[(size_t)(off + cstart + (e >> 6)) * 64 + (e & 63)]);
        CP_COMMIT();
        if (1 < ntiles) {
            int ns = cstart + TILE;
            int tn1 = min(TILE, cend - ns);
            for (int e = t; e < tn1 * 64; e += 256)
                cp_async16(&xs4[2080 + (e >> 6) * 65 + (e & 63)],
                           &X4[(size_t)(off + ns + (e >> 6)) * 64 + (e & 63)]);
        }
        CP_COMMIT();
    }

    int lane = t & 31;
    int w    = t >> 5;
    int g    = lane >> 2;      // groupID
    int tid4 = lane & 3;       // threadID in group
    int mh   = w & 1;          // score m-half
    int kq   = w >> 1;         // score K-quarter
    int m0   = mh * 16;

    // persistent B fragments (A-matrix)
    unsigned bf[8][2][2];
    #pragma unroll
    for (int j = 0; j < 8; j++) {
        int k0 = kq * 64 + j * 8;
        #pragma unroll
        for (int nt = 0; nt < 2; nt++) {
            int sh = nt * 8 + g;
            bf[j][nt][0] = f2tf32(g_As[sh * 260 + k0 + tid4]);
            bf[j][nt][1] = f2tf32(g_As[sh * 260 + k0 + tid4 + 4]);
        }
    }

    float runs = 0.f;   // per-thread partial; cross-lane reduce after loop
    float yc[4][4];
    #pragma unroll
    for (int nt = 0; nt < 4; nt++)
        #pragma unroll
        for (int q = 0; q < 4; q++) yc[nt][q] = 0.f;

    int mysh = w + (((t >> 4) & 1) << 3);
    int myn  = lane & 15;

    int bi = 0;
    for (int i = 0; i < ntiles; i++) {
        CP_WAIT1();
        __syncthreads();
        int tn = min(TILE, cend - (cstart + i * TILE));

        if (i + 2 < ntiles) {
            int ns = cstart + (i + 2) * TILE;
            int tnn = min(TILE, cend - ns);
            int bn = bi + 2; if (bn >= 3) bn -= 3;
            for (int e = t; e < tnn * 64; e += 256)
                cp_async16(&xs4[bn * 2080 + (e >> 6) * 65 + (e & 63)],
                           &X4[(size_t)(off + ns + (e >> 6)) * 64 + (e & 63)]);
        }
        CP_COMMIT();

        // ---- score phase: tf32 mma, warp = (m-half, K-quarter) ----
        {
            float acc0[4] = {0.f, 0.f, 0.f, 0.f};
            float acc1[4] = {0.f, 0.f, 0.f, 0.f};
            const float* xb = xs + bi * 8320;
            #pragma unroll
            for (int j = 0; j < 8; j++) {
                int k0 = kq * 64 + j * 8;
                const float* xa = xb + (m0 + g) * 260 + k0 + tid4;
                unsigned af[4];
                af[0] = f2tf32(xa[0]);
                af[1] = f2tf32(xa[8 * 260]);
                af[2] = f2tf32(xa[4]);
                af[3] = f2tf32(xa[8 * 260 + 4]);
                mma_tf32(acc0, af, bf[j][0]);
                mma_tf32(acc1, af, bf[j][1]);
            }
            float* sp = scoreP + kq * 544;
            int n0 = m0 + g, n1 = m0 + 8 + g;
            sp[n0 * 17 + 2 * tid4]     = acc0[0];
            sp[n0 * 17 + 2 * tid4 + 1] = acc0[1];
            sp[n1 * 17 + 2 * tid4]     = acc0[2];
            sp[n1 * 17 + 2 * tid4 + 1] = acc0[3];
            sp[n0 * 17 + 8 + 2 * tid4]     = acc1[0];
            sp[n0 * 17 + 8 + 2 * tid4 + 1] = acc1[1];
            sp[n1 * 17 + 8 + 2 * tid4]     = acc1[2];
            sp[n1 * 17 + 8 + 2 * tid4 + 1] = acc1[3];
        }
        __syncthreads();

        // ---- flat softmax: scores bounded (|s| << 60), no max needed ----
        {
            int n1 = myn, n2 = myn + 16;
            bool v1 = n1 < tn, v2 = n2 < tn;
            float e1 = 0.f, e2 = 0.f;
            if (v1) {
                float s1 = scoreP[n1 * 17 + mysh] + scoreP[544 + n1 * 17 + mysh]
                         + scoreP[1088 + n1 * 17 + mysh] + scoreP[1632 + n1 * 17 + mysh];
                e1 = __expf(s1);
            }
            if (v2) {
                float s2 = scoreP[n2 * 17 + mysh] + scoreP[544 + n2 * 17 + mysh]
                         + scoreP[1088 + n2 * 17 + mysh] + scoreP[1632 + n2 * 17 + mysh];
                e2 = __expf(s2);
            }
            scE[n1 * 16 + mysh] = e1;       // always write: zero for invalid lanes
            scE[n2 * 16 + mysh] = e2;
            runs += e1 + e2;                // lane-local; reduced once after loop
        }
        __syncthreads();

        // ---- y-pass: tf32 mma, warp owns 32 columns (no rescale) ----
        {
            const float* xb = xs + bi * 8320;
            #pragma unroll
            for (int kk2 = 0; kk2 < 4; kk2++) {
                unsigned af[4];
                af[0] = f2tf32(scE[(kk2 * 8 + tid4) * 16 + g]);
                af[1] = f2tf32(scE[(kk2 * 8 + tid4) * 16 + g + 8]);
                af[2] = f2tf32(scE[(kk2 * 8 + tid4 + 4) * 16 + g]);
                af[3] = f2tf32(scE[(kk2 * 8 + tid4 + 4) * 16 + g + 8]);
                const float* xrow0 = xb + (kk2 * 8 + tid4) * 260 + w * 32 + g;
                const float* xrow1 = xb + (kk2 * 8 + tid4 + 4) * 260 + w * 32 + g;
                #pragma unroll
                for (int nt = 0; nt < 4; nt++) {
                    unsigned bfr[2];
                    bfr[0] = f2tf32(xrow0[nt * 8]);
                    bfr[1] = f2tf32(xrow1[nt * 8]);
                    mma_tf32(yc[nt], af, bfr);
                }
            }
        }
        if (++bi >= 3) bi = 0;
        // next-iteration top barrier doubles as the post-y fence
    }
    __syncthreads();

    {
        float ssum = runs;
        ssum += __shfl_xor_sync(0xffffffffu, ssum, 1);
        ssum += __shfl_xor_sync(0xffffffffu, ssum, 2);
        ssum += __shfl_xor_sync(0xffffffffu, ssum, 4);
        ssum += __shfl_xor_sync(0xffffffffu, ssum, 8);
        if (myn == 0) g_csum[bid * 16 + mysh] = ssum;
    }
    {
        #pragma unroll
        for (int nt = 0; nt < 4; nt++) {
            int colb = w * 32 + nt * 8 + 2 * tid4;
            float* p0 = &g_cy[((size_t)bid * 16 + g) * 256 + colb];
            float* p1 = &g_cy[((size_t)bid * 16 + g + 8) * 256 + colb];
            *(float2*)p0 = make_float2(yc[nt][0], yc[nt][1]);
            *(float2*)p1 = make_float2(yc[nt][2], yc[nt][3]);
        }
    }
}

// ---------------- combine: 512 threads, G=2, 128 blocks (R15-proven) -------------
// dyn smem floats: ysP[8192] att[2048] hbuf[512] itot[32] part[4096] = 14880
#define COMB_SMEM_F 14880
__global__ __launch_bounds__(512) void k_comb(float* __restrict__ out,
                                              const float* __restrict__ fc1b,
                                              const float* __restrict__ fc2b)
{
    extern __shared__ __align__(16) float smc[];
    float* ysP  = smc;            // [g][h][j][s] as float4 over s
    float* att  = smc + 8192;     // [g][s*256+i]
    float* hbuf = smc + 10240;
    float* itot = smc + 10752;
    float* part = smc + 10784;    // 4096 scratch

    int t = threadIdx.x;
    int col = t & 255;
    int half = t >> 8;
    int b0 = blockIdx.x * 2;

    if (half == 0 && col < 32) {
        int g = col >> 4, sh = col & 15;
        int b = b0 + g;
        float tot = g_csum[(b * NCH + 0) * 16 + sh] + g_csum[(b * NCH + 1) * 16 + sh]
                  + g_csum[(b * NCH + 2) * 16 + sh] + g_csum[(b * NCH + 3) * 16 + sh];
        itot[g * 16 + sh] = 1.f / tot;
    }
    __syncthreads();

    // ysP fill: half h does sh range [h*8, h*8+8); plain sum over chunks
    for (int g = 0; g < 2; g++) {
        int b = b0 + g;
        #pragma unroll
        for (int s8 = 0; s8 < 8; s8++) {
            int sh = half * 8 + s8;
            float acc = g_cy[((b * NCH + 0) * 16 + sh) * 256 + col]
                      + g_cy[((b * NCH + 1) * 16 + sh) * 256 + col]
                      + g_cy[((b * NCH + 2) * 16 + sh) * 256 + col]
                      + g_cy[((b * NCH + 3) * 16 + sh) * 256 + col];
            float yv = acc * itot[g * 16 + sh];
            ysP[(((g * 4 + (sh & 3)) * 256 + col) << 2) + (sh >> 2)] = yv;
        }
    }
    __syncthreads();

    // W2T phase: half h does heads {2h, 2h+1}; partials combined in smem
    {
        float a[8];
        #pragma unroll
        for (int i = 0; i < 8; i++) a[i] = 0.f;
        #pragma unroll
        for (int hh = 0; hh < 2; hh++) {
            int h = half * 2 + hh;
            const float* wpA = g_W2T + h * 65536 + col;
            const float* wpB = wpA + 128 * 256;
            const float4* y0 = (const float4*)ysP + (0 * 4 + h) * 256;
            const float4* y1 = (const float4*)ysP + (1 * 4 + h) * 256;
            #pragma unroll 16
            for (int j = 0; j < 128; j++) {
                float wA = wpA[j * 256];
                float wB = wpB[j * 256];
                float4 pA0 = y0[j],       pA1 = y1[j];
                float4 pB0 = y0[j + 128], pB1 = y1[j + 128];
                a[0] += wA * pA0.x + wB * pB0.x; a[1] += wA * pA0.y + wB * pB0.y;
                a[2] += wA * pA0.z + wB * pB0.z; a[3] += wA * pA0.w + wB * pB0.w;
                a[4] += wA * pA1.x + wB * pB1.x; a[5] += wA * pA1.y + wB * pB1.y;
                a[6] += wA * pA1.z + wB * pB1.z; a[7] += wA * pA1.w + wB * pB1.w;
            }
        }
        #pragma unroll
        for (int i = 0; i < 8; i++)
            part[half * 2048 + i * 256 + col] = a[i];
    }
    __syncthreads();
    if (half == 0) {
        float ca = g_cAtt[col];
        #pragma unroll
        for (int i = 0; i < 8; i++) {
            float v = part[i * 256 + col] + part[2048 + i * 256 + col] + ca;
            att[(i >> 2) * 1024 + (i & 3) * 256 + col] = v;
        }
    }
    __syncthreads();

    // fc1: half h does j range [h*512, h*512+512) with dual streams
    {
        float p0 = 0.f, p1 = 0.f, q0 = 0.f, q1 = 0.f;
        const float* w1A = g_fc1T + (half * 512) * 256 + col;
        const float* w1B = w1A + 256 * 256;
        const float* attA = att + half * 512;
        const float* attB = attA + 256;
        #pragma unroll 16
        for (int j = 0; j < 256; j++) {
            float wA = w1A[j * 256];
            float wB = w1B[j * 256];
            p0 += wA * attA[j];        q0 += wB * attB[j];
            p1 += wA * attA[1024 + j]; q1 += wB * attB[1024 + j];
        }
        part[(half * 2 + 0) * 256 + col] = p0 + q0;
        part[(half * 2 + 1) * 256 + col] = p1 + q1;
    }
    __syncthreads();
    if (half == 0) {
        #pragma unroll
        for (int g = 0; g < 2; g++) {
            float pre = fc1b[col] + part[g * 256 + col] + part[(2 + g) * 256 + col];
            hbuf[g * 256 + col] = 0.5f * pre * (1.f + erff(pre * 0.70710678118f));
        }
    }
    __syncthreads();

    // fc2: half h does j range [h*128, h*128+128) with dual streams
    {
        float o0 = 0.f, o1 = 0.f, r0 = 0.f, r1 = 0.f;
        const float* w2A = g_fc2T + (half * 128) * 256 + col;
        const float* w2B = w2A + 64 * 256;
        const float* hA = hbuf + half * 128;
        const float* hB = hA + 64;
        #pragma unroll 16
        for (int j = 0; j < 64; j++) {
            float wA = w2A[j * 256];
            float wB = w2B[j * 256];
            o0 += wA * hA[j];        r0 += wB * hB[j];
            o1 += wA * hA[256 + j];  r1 += wB * hB[256 + j];
        }
        part[1024 + (half * 2 + 0) * 256 + col] = o0 + r0;
        part[1024 + (half * 2 + 1) * 256 + col] = o1 + r1;
    }
    __syncthreads();
    if (half == 0) {
        #pragma unroll
        for (int g = 0; g < 2; g++)
            out[(b0 + g) * 256 + col] = fc2b[col]
                + part[1024 + g * 256 + col] + part[1024 + (2 + g) * 256 + col];
    }
}

// ---------------- launch --------------------------------------------------------
extern "C" void kernel_launch(void* const* d_in, const int* in_sizes, int n_in,
                              void* d_out, int out_size)
{
    const float* X     = (const float*)d_in[0];
    const int*   cnt   = (const int*)  d_in[1];
    const float* seeds = (const float*)d_in[2];
    const float* inW   = (const float*)d_in[3];
    const float* inB   = (const float*)d_in[4];
    const float* outW  = (const float*)d_in[5];
    const float* outB  = (const float*)d_in[6];
    const float* fc1w  = (const float*)d_in[7];
    const float* fc1b  = (const float*)d_in[8];
    const float* fc2w  = (const float*)d_in[9];
    const float* fc2b  = (const float*)d_in[10];
    float* out = (float*)d_out;

    cudaFuncSetAttribute(k_attn, cudaFuncAttributeMaxDynamicSharedMemorySize,
                         ATTN_SMEM_F * 4);
    cudaFuncSetAttribute(k_comb, cudaFuncAttributeMaxDynamicSharedMemorySize,
                         COMB_SMEM_F * 4);

    k_proA<<<65, 256>>>(cnt, seeds, inW, inB, outW, outB);
    k_attn<<<N_ATTN + 576, 256, ATTN_SMEM_F * 4>>>(X, inW, outW, fc1w, fc2w);
    k_comb<<<128, 512, COMB_SMEM_F * 4>>>(out, fc1b, fc2b);
}